// round 13
// baseline (speedup 1.0000x reference)
#include <cuda_runtime.h>
#include <cuda_bf16.h>
#include <cstdint>

#define NX    512
#define NU    128
#define ND    64
#define BATCH 256
#define TT    256
#define NCTA  128

typedef unsigned long long ull;

// ---------------- device scratch (allocation-free) ----------------
__device__ float g_R[NX * NX];   // R[k][j] = W_eff[j][k]

// ---------------- helpers ----------------
__device__ __forceinline__ void ffma2(ull& acc, ull a, ull b) {
    asm volatile("fma.rn.f32x2 %0, %1, %2, %0;" : "+l"(acc) : "l"(a), "l"(b));
}
__device__ __forceinline__ float hsum2(ull v) {
    float lo, hi;
    asm("mov.b64 {%0, %1}, %2;" : "=f"(lo), "=f"(hi) : "l"(v));
    return lo + hi;
}
__device__ __forceinline__ ull pack2(float lo, float hi) {
    ull v; asm("mov.b64 %0, {%1, %2};" : "=l"(v) : "f"(lo), "f"(hi)); return v;
}
__device__ __forceinline__ float4 ld_cg_f4(const float* p) {
    float4 v;
    asm volatile("ld.global.cg.v4.f32 {%0,%1,%2,%3}, [%4];"
                 : "=f"(v.x), "=f"(v.y), "=f"(v.z), "=f"(v.w) : "l"(p));
    return v;
}
__device__ __forceinline__ void st_cg_f4(float* p, float4 v) {
    asm volatile("st.global.cg.v4.f32 [%0], {%1,%2,%3,%4};"
                 :: "l"(p), "f"(v.x), "f"(v.y), "f"(v.z), "f"(v.w));
}
__device__ __forceinline__ uint32_t smem_u32(const void* p) {
    uint32_t a;
    asm("{ .reg .u64 t; cvta.to.shared.u64 t, %1; cvt.u32.u64 %0, t; }" : "=r"(a) : "l"(p));
    return a;
}
__device__ __forceinline__ uint32_t mapa_u32(uint32_t a, uint32_t rank) {
    uint32_t r;
    asm("mapa.shared::cluster.u32 %0, %1, %2;" : "=r"(r) : "r"(a), "r"(rank));
    return r;
}
__device__ __forceinline__ void st_cluster_u64(uint32_t a, ull v) {
    asm volatile("st.shared::cluster.u64 [%0], %1;" :: "r"(a), "l"(v) : "memory");
}
__device__ __forceinline__ void cluster_sync() {
    asm volatile("barrier.cluster.arrive.aligned;" ::: "memory");
    asm volatile("barrier.cluster.wait.aligned;" ::: "memory");
}

// ---------------- kernel 1: W_eff prep ----------------
__global__ void __launch_bounds__(256) prep_kernel(const float* __restrict__ Aw,
                                                   const float* __restrict__ As) {
    int k = blockIdx.x;
    int tid = threadIdx.x;
    __shared__ float red[256];
    const float* row = Aw + (size_t)k * NX;
    float a0 = row[tid], a1 = row[tid + 256];
    red[tid] = fmaxf(a0, a1);
    __syncthreads();
    for (int s = 128; s > 0; s >>= 1) {
        if (tid < s) red[tid] = fmaxf(red[tid], red[tid + s]);
        __syncthreads();
    }
    float mx = red[0];
    __syncthreads();
    float e0 = expf(a0 - mx), e1 = expf(a1 - mx);
    red[tid] = e0 + e1;
    __syncthreads();
    for (int s = 128; s > 0; s >>= 1) {
        if (tid < s) red[tid] += red[tid + s];
        __syncthreads();
    }
    float inv = 1.0f / red[0];
    const float* srow = As + (size_t)k * NX;
    float z0 = srow[tid], z1 = srow[tid + 256];
    float s0 = 1.0f - 0.1f / (1.0f + expf(-z0));
    float s1 = 1.0f - 0.1f / (1.0f + expf(-z1));
    g_R[(size_t)k * NX + tid]       = s0 * e0 * inv;
    g_R[(size_t)k * NX + tid + 256] = s1 * e1 * inv;
}

// ---------------- kernel 2: injection GEMM (in-place into X) ----------------
#define INJ_AS   68
#define INJ_WS   194
#define INJ_SMEM ((64 * INJ_AS + 64 * INJ_WS) * 4)

__global__ void __launch_bounds__(256) inj_kernel(
    const float* __restrict__ U, const float* __restrict__ D,
    const float* __restrict__ Bw, const float* __restrict__ Ew,
    float* __restrict__ X)
{
    extern __shared__ float sm[];
    float* A_s = sm;
    float* W_s = sm + 64 * INJ_AS;
    int tid = threadIdx.x;
    int n0  = blockIdx.x * 64;
    size_t m0 = (size_t)blockIdx.y * 64;

    for (int i = tid; i < 64 * 192; i += 256) {
        int n = i / 192, k = i - n * 192;
        float v = (k < 128) ? Bw[(size_t)(n0 + n) * NU + k]
                            : Ew[(size_t)(n0 + n) * ND + (k - 128)];
        W_s[n * INJ_WS + k] = v;
    }

    int tn = tid & 15, tm = tid >> 4;
    ull acc[16];
#pragma unroll
    for (int i = 0; i < 16; i++) acc[i] = 0ull;

    for (int kc = 0; kc < 3; kc++) {
        __syncthreads();
        const float* src; int stride;
        if (kc < 2) { src = U + m0 * NU + kc * 64; stride = NU; }
        else        { src = D + m0 * ND;           stride = ND; }
        for (int i = tid; i < 1024; i += 256) {
            int r = i >> 4, c = i & 15;
            *(float4*)(A_s + r * INJ_AS + c * 4) =
                *(const float4*)(src + (size_t)r * stride + c * 4);
        }
        __syncthreads();
#pragma unroll
        for (int kp = 0; kp < 32; kp++) {
            ull a[4], w[4];
#pragma unroll
            for (int i = 0; i < 4; i++)
                a[i] = *(const ull*)(A_s + (tm * 4 + i) * INJ_AS + 2 * kp);
#pragma unroll
            for (int j = 0; j < 4; j++)
                w[j] = *(const ull*)(W_s + (tn + 16 * j) * INJ_WS + kc * 64 + 2 * kp);
#pragma unroll
            for (int i = 0; i < 4; i++)
#pragma unroll
                for (int j = 0; j < 4; j++)
                    ffma2(acc[i * 4 + j], a[i], w[j]);
        }
    }
#pragma unroll
    for (int i = 0; i < 4; i++) {
        size_t m = m0 + tm * 4 + i;
#pragma unroll
        for (int j = 0; j < 4; j++)
            X[m * NX + n0 + tn + 16 * j] = hsum2(acc[i * 4 + j]);
    }
}

// ---------------- kernel 3: persistent scan; cluster-8 DSMEM scatter exchange ----------------
// 16 clusters x 8 CTAs. CTA rank gj computes out-cols [gj*64, gj*64+64) for 16 batches,
// and stores its tile directly into all 8 peers' next x buffer (plain DSMEM stores);
// cluster.sync provides the release/acquire edge and replaces fence+atomic barrier+staging.
#define WSTRIDE   65
#define W_BYTES   (128 * WSTRIDE * 16)          // 133120
#define BUF_B     (16 * NX * 4)                 // 32768 per buffer (x2)
#define RED_OFF   (W_BYTES + 2 * BUF_B)
#define SCAN_SMEM (RED_OFF + 8 * 16 * 64 * 4)   // 231424 <= 232448

__global__ void __launch_bounds__(256, 1) __cluster_dims__(8, 1, 1)
scan_kernel(const float* __restrict__ x0, float* __restrict__ X, float* __restrict__ Y)
{
    extern __shared__ char smraw[];
    ulonglong2* Wsm  = (ulonglong2*)smraw;                 // [q*WSTRIDE + k_local]
    char*       bufc = smraw + W_BYTES;                    // two 32KB x buffers
    float*      red  = (float*)(smraw + RED_OFF);          // [w][b][k_local]

    const int tid  = threadIdx.x;
    const int lane = tid & 31;
    const int warp = tid >> 5;        // j-eighth: q in [warp*16, warp*16+16)
    const int gj   = blockIdx.x & 7;  // cluster rank; out cols [gj*64, gj*64+64)
    const int gb   = blockIdx.x >> 3; // batch group [gb*16, gb*16+16)
    const int rb   = tid >> 4;        // batch row 0..15
    const int kq   = tid & 15;        // k quad: cols kq*4 .. kq*4+3

    const uint32_t smem_base = smem_u32(smraw);

    // pin W slice: Wsm[q*WSTRIDE+kk] = R[gj*64+kk][4q .. 4q+3]
    for (int i = tid; i < 64 * 128; i += 256) {
        int kk = i >> 7, q = i & 127;
        float4 v = *(const float4*)(g_R + (size_t)(gj * 64 + kk) * NX + 4 * q);
        ((float4*)Wsm)[q * WSTRIDE + kk] = v;
    }
    // stage x0 into buffer 0
    for (int i = tid; i < 2048; i += 256) {
        int b = i >> 7, c = i & 127;
        ((float4*)bufc)[b * 128 + c] = *(const float4*)(x0 + (size_t)(gb * 16 + b) * NX + 4 * c);
    }
    __syncthreads();
    cluster_sync();   // all peers resident & prologues done before any DSMEM traffic

#pragma unroll 1
    for (int t = 0; t < TT; t++) {
        const int bsel = t & 1;
        // ---- compute: packed even/odd-j partial sums, k = lane / lane+32 ----
        ulonglong2* xb = (ulonglong2*)(bufc + bsel * BUF_B);
        ull accA[16], accB[16];
#pragma unroll
        for (int b = 0; b < 16; b++) { accA[b] = 0ull; accB[b] = 0ull; }
        const int q0 = warp * 16;
#pragma unroll 4
        for (int q = q0; q < q0 + 16; q++) {
            ulonglong2 wa = Wsm[q * WSTRIDE + lane];
            ulonglong2 wb = Wsm[q * WSTRIDE + lane + 32];
#pragma unroll
            for (int b = 0; b < 16; b++) {
                ulonglong2 xp = xb[b * 128 + q];    // warp-broadcast
                ffma2(accA[b], xp.x, wa.x);
                ffma2(accA[b], xp.y, wa.y);
                ffma2(accB[b], xp.x, wb.x);
                ffma2(accB[b], xp.y, wb.y);
            }
        }
        // ---- partials ----
#pragma unroll
        for (int b = 0; b < 16; b++) {
            red[(warp * 16 + b) * 64 + lane]      = hsum2(accA[b]);
            red[(warp * 16 + b) * 64 + lane + 32] = hsum2(accB[b]);
        }
        __syncthreads();
        // ---- reduce 8 warps + inj; write X, Y; scatter to peers' next buffer ----
        float* Xt = X + ((size_t)t * BATCH + gb * 16) * NX + gj * 64;
        float4 s4 = ld_cg_f4(Xt + (size_t)rb * NX + kq * 4);   // inj (stable since inj_kernel)
#pragma unroll
        for (int w = 0; w < 8; w++) {
            float4 rv = ((float4*)red)[(w * 16 + rb) * 16 + kq];
            s4.x += rv.x; s4.y += rv.y; s4.z += rv.z; s4.w += rv.w;
        }
        st_cg_f4(Xt + (size_t)rb * NX + kq * 4, s4);
        if (gj == 7 && kq == 15)
            Y[(size_t)t * BATCH + gb * 16 + rb] = s4.w;        // col 511
        if (t + 1 < TT) {
            uint32_t loc = smem_base + (uint32_t)(W_BYTES + ((t + 1) & 1) * BUF_B
                          + (rb * 512 + gj * 64 + kq * 4) * 4);
            ull v0 = pack2(s4.x, s4.y), v1 = pack2(s4.z, s4.w);
#pragma unroll
            for (int c = 0; c < 8; c++) {
                uint32_t d = mapa_u32(loc, (uint32_t)c);
                st_cluster_u64(d,     v0);
                st_cluster_u64(d + 8, v1);
            }
        } else {
            break;
        }
        // ---- cluster barrier: release scatter writes, acquire peers' ----
        cluster_sync();
    }

    cluster_sync();   // no CTA exits while peers may still target its SMEM
}

// ---------------- launch ----------------
extern "C" void kernel_launch(void* const* d_in, const int* in_sizes, int n_in,
                              void* d_out, int out_size) {
    const float* x0 = (const float*)d_in[0];
    const float* U  = (const float*)d_in[1];
    const float* D  = (const float*)d_in[2];
    const float* Aw = (const float*)d_in[3];
    const float* As = (const float*)d_in[4];
    const float* Bw = (const float*)d_in[5];
    const float* Ew = (const float*)d_in[6];
    float* X = (float*)d_out;                   // [T][BATCH][NX]
    float* Y = X + (size_t)TT * BATCH * NX;     // [T][BATCH]

    cudaFuncSetAttribute(inj_kernel,  cudaFuncAttributeMaxDynamicSharedMemorySize, INJ_SMEM);
    cudaFuncSetAttribute(scan_kernel, cudaFuncAttributeMaxDynamicSharedMemorySize, SCAN_SMEM);

    prep_kernel<<<NX, 256>>>(Aw, As);
    inj_kernel<<<dim3(8, (TT * BATCH) / 64), 256, INJ_SMEM>>>(U, D, Bw, Ew, X);
    scan_kernel<<<NCTA, 256, SCAN_SMEM>>>(x0, X, Y);
}

// round 15
// speedup vs baseline: 2.1918x; 2.1918x over previous
#include <cuda_runtime.h>
#include <cuda_bf16.h>
#include <cstdint>

#define NX    512
#define NU    128
#define ND    64
#define BATCH 256
#define TT    256
#define NCTA  128

typedef unsigned long long ull;

// ---------------- device scratch (allocation-free) ----------------
__device__ float    g_R[NX * NX];       // R[k][j] = W_eff[j][k]
__device__ unsigned g_cnt[16 * 32];     // per-batch-group monotonic counters (128B apart)

// ---------------- helpers ----------------
__device__ __forceinline__ void ffma2(ull& acc, ull a, ull b) {
    asm volatile("fma.rn.f32x2 %0, %1, %2, %0;" : "+l"(acc) : "l"(a), "l"(b));
}
__device__ __forceinline__ float hsum2(ull v) {
    float lo, hi;
    asm("mov.b64 {%0, %1}, %2;" : "=f"(lo), "=f"(hi) : "l"(v));
    return lo + hi;
}
__device__ __forceinline__ float4 ld_cg_f4(const float* p) {
    float4 v;
    asm volatile("ld.global.cg.v4.f32 {%0,%1,%2,%3}, [%4];"
                 : "=f"(v.x), "=f"(v.y), "=f"(v.z), "=f"(v.w) : "l"(p));
    return v;
}
__device__ __forceinline__ void st_cg_f4(float* p, float4 v) {
    asm volatile("st.global.cg.v4.f32 [%0], {%1,%2,%3,%4};"
                 :: "l"(p), "f"(v.x), "f"(v.y), "f"(v.z), "f"(v.w));
}

// ---------------- kernel 1: W_eff prep (+ counter reset) ----------------
__global__ void __launch_bounds__(256) prep_kernel(const float* __restrict__ Aw,
                                                   const float* __restrict__ As) {
    int k = blockIdx.x;
    int tid = threadIdx.x;
    if (k == 0 && tid < 16) g_cnt[tid * 32] = 0;     // graph-replay-safe reset
    __shared__ float red[256];
    const float* row = Aw + (size_t)k * NX;
    float a0 = row[tid], a1 = row[tid + 256];
    red[tid] = fmaxf(a0, a1);
    __syncthreads();
    for (int s = 128; s > 0; s >>= 1) {
        if (tid < s) red[tid] = fmaxf(red[tid], red[tid + s]);
        __syncthreads();
    }
    float mx = red[0];
    __syncthreads();
    float e0 = expf(a0 - mx), e1 = expf(a1 - mx);
    red[tid] = e0 + e1;
    __syncthreads();
    for (int s = 128; s > 0; s >>= 1) {
        if (tid < s) red[tid] += red[tid + s];
        __syncthreads();
    }
    float inv = 1.0f / red[0];
    const float* srow = As + (size_t)k * NX;
    float z0 = srow[tid], z1 = srow[tid + 256];
    float s0 = 1.0f - 0.1f / (1.0f + expf(-z0));
    float s1 = 1.0f - 0.1f / (1.0f + expf(-z1));
    g_R[(size_t)k * NX + tid]       = s0 * e0 * inv;
    g_R[(size_t)k * NX + tid + 256] = s1 * e1 * inv;
}

// ---------------- kernel 2: injection GEMM (in-place into X) ----------------
#define INJ_AS   68
#define INJ_WS   194
#define INJ_SMEM ((64 * INJ_AS + 64 * INJ_WS) * 4)

__global__ void __launch_bounds__(256) inj_kernel(
    const float* __restrict__ U, const float* __restrict__ D,
    const float* __restrict__ Bw, const float* __restrict__ Ew,
    float* __restrict__ X)
{
    extern __shared__ float sm[];
    float* A_s = sm;
    float* W_s = sm + 64 * INJ_AS;
    int tid = threadIdx.x;
    int n0  = blockIdx.x * 64;
    size_t m0 = (size_t)blockIdx.y * 64;

    for (int i = tid; i < 64 * 192; i += 256) {
        int n = i / 192, k = i - n * 192;
        float v = (k < 128) ? Bw[(size_t)(n0 + n) * NU + k]
                            : Ew[(size_t)(n0 + n) * ND + (k - 128)];
        W_s[n * INJ_WS + k] = v;
    }

    int tn = tid & 15, tm = tid >> 4;
    ull acc[16];
#pragma unroll
    for (int i = 0; i < 16; i++) acc[i] = 0ull;

    for (int kc = 0; kc < 3; kc++) {
        __syncthreads();
        const float* src; int stride;
        if (kc < 2) { src = U + m0 * NU + kc * 64; stride = NU; }
        else        { src = D + m0 * ND;           stride = ND; }
        for (int i = tid; i < 1024; i += 256) {
            int r = i >> 4, c = i & 15;
            *(float4*)(A_s + r * INJ_AS + c * 4) =
                *(const float4*)(src + (size_t)r * stride + c * 4);
        }
        __syncthreads();
#pragma unroll
        for (int kp = 0; kp < 32; kp++) {
            ull a[4], w[4];
#pragma unroll
            for (int i = 0; i < 4; i++)
                a[i] = *(const ull*)(A_s + (tm * 4 + i) * INJ_AS + 2 * kp);
#pragma unroll
            for (int j = 0; j < 4; j++)
                w[j] = *(const ull*)(W_s + (tn + 16 * j) * INJ_WS + kc * 64 + 2 * kp);
#pragma unroll
            for (int i = 0; i < 4; i++)
#pragma unroll
                for (int j = 0; j < 4; j++)
                    ffma2(acc[i * 4 + j], a[i], w[j]);
        }
    }
#pragma unroll
    for (int i = 0; i < 4; i++) {
        size_t m = m0 + tm * 4 + i;
#pragma unroll
        for (int j = 0; j < 4; j++)
            X[m * NX + n0 + tn + 16 * j] = hsum2(acc[i * 4 + j]);
    }
}

// ---------------- kernel 3: persistent scan (R4 base + exchange micro-cuts) ----------------
// 128 CTAs = 16 batch-groups (16 b) x 8 k-groups (64 cols).
#define W_BYTES   (128 * 66 * 16)
#define XS_BYTES  (16 * NX * 4)
#define SCAN_SMEM (W_BYTES + XS_BYTES + 8 * 16 * 64 * 4)

__global__ void __launch_bounds__(256, 1) scan_kernel(
    const float* __restrict__ x0, float* __restrict__ X, float* __restrict__ Y)
{
    extern __shared__ char smraw[];
    ulonglong2* Wsm   = (ulonglong2*)smraw;                    // [q*66 + k_local]
    float4*     x_s4  = (float4*)(smraw + W_BYTES);            // [b*128 + q]
    ulonglong2* x_su2 = (ulonglong2*)(smraw + W_BYTES);
    float*      red   = (float*)(smraw + W_BYTES + XS_BYTES);  // [w][b][k_local]
    float4*     red4  = (float4*)red;

    const int tid  = threadIdx.x;
    const int lane = tid & 31;
    const int warp = tid >> 5;        // j-eighth: q in [warp*16, warp*16+16)
    const int gj   = blockIdx.x & 7;  // out cols [gj*64, gj*64+64)
    const int gb   = blockIdx.x >> 3; // batches  [gb*16, gb*16+16)
    const int rb   = tid >> 4;        // batch row 0..15 (reduce phase)
    const int kq   = tid & 15;        // k quad (reduce phase)
    unsigned* cnt  = &g_cnt[gb * 32];

    // pin W slice: Wsm[q*66+kk] = R[gj*64+kk][4q .. 4q+3] (two packed j-pairs)
    for (int i = tid; i < 64 * 128; i += 256) {
        int kk = i >> 7, q = i & 127;
        float4 v = *(const float4*)(g_R + (size_t)(gj * 64 + kk) * NX + 4 * q);
        ((float4*)Wsm)[q * 66 + kk] = v;
    }
    // stage x0
    for (int i = tid; i < 2048; i += 256) {
        int b = i >> 7, c = i & 127;
        x_s4[b * 128 + c] = *(const float4*)(x0 + (size_t)(gb * 16 + b) * NX + 4 * c);
    }
    __syncthreads();

#pragma unroll 1
    for (int t = 0; t < TT; t++) {
        // ---- compute: packed even/odd-j partial sums, k = lane / lane+32 ----
        ull accA[16], accB[16];
#pragma unroll
        for (int b = 0; b < 16; b++) { accA[b] = 0ull; accB[b] = 0ull; }
        const int q0 = warp * 16;
#pragma unroll 4
        for (int q = q0; q < q0 + 16; q++) {
            ulonglong2 wa = Wsm[q * 66 + lane];
            ulonglong2 wb = Wsm[q * 66 + lane + 32];
#pragma unroll
            for (int b = 0; b < 16; b++) {
                ulonglong2 xp = x_su2[b * 128 + q];    // warp-broadcast
                ffma2(accA[b], xp.x, wa.x);
                ffma2(accA[b], xp.y, wa.y);
                ffma2(accB[b], xp.x, wb.x);
                ffma2(accB[b], xp.y, wb.y);
            }
        }
        // ---- partials ----
#pragma unroll
        for (int b = 0; b < 16; b++) {
            red[(warp * 16 + b) * 64 + lane]      = hsum2(accA[b]);
            red[(warp * 16 + b) * 64 + lane + 32] = hsum2(accB[b]);
        }
        __syncthreads();
        // ---- reduce 8 warps + inj (float4 path, proven in R8/R13) ----
        float* Xt = X + ((size_t)t * BATCH + gb * 16) * NX + gj * 64;
        float4 s4 = ld_cg_f4(Xt + (size_t)rb * NX + kq * 4);
#pragma unroll
        for (int w = 0; w < 8; w++) {
            float4 rv = red4[(w * 16 + rb) * 16 + kq];
            s4.x += rv.x; s4.y += rv.y; s4.z += rv.z; s4.w += rv.w;
        }
        st_cg_f4(Xt + (size_t)rb * NX + kq * 4, s4);
        if (gj == 7 && kq == 15)
            Y[(size_t)t * BATCH + gb * 16 + rb] = s4.w;        // col 511
        if (t == TT - 1) break;
        // ---- group barrier: CG grid.sync pattern (single fence, tid0 only) ----
        __syncthreads();
        if (tid == 0) {
            __threadfence();                              // release (cumulative via bar)
            atomicAdd(cnt, 1u);
            unsigned target = 8u * (unsigned)(t + 1);
            while (atomicAdd(cnt, 0u) < target) { }       // strong-read poll
            __threadfence();                              // acquire
        }
        __syncthreads();
        // ---- per-warp staging: warp w stages exactly its consumed q-slice ----
        {
            const float* src = X + ((size_t)t * BATCH + gb * 16) * NX;
#pragma unroll
            for (int r = 0; r < 8; r++) {
                int i = lane + 32 * r;              // 0..255
                int b = i >> 4, qq = i & 15;
                int q = warp * 16 + qq;
                x_s4[b * 128 + q] = ld_cg_f4(src + (size_t)b * NX + 4 * q);
            }
            // no syncthreads: slice producer == sole consumer (warp-private)
        }
    }
}

// ---------------- launch ----------------
extern "C" void kernel_launch(void* const* d_in, const int* in_sizes, int n_in,
                              void* d_out, int out_size) {
    const float* x0 = (const float*)d_in[0];
    const float* U  = (const float*)d_in[1];
    const float* D  = (const float*)d_in[2];
    const float* Aw = (const float*)d_in[3];
    const float* As = (const float*)d_in[4];
    const float* Bw = (const float*)d_in[5];
    const float* Ew = (const float*)d_in[6];
    float* X = (float*)d_out;                   // [T][BATCH][NX]
    float* Y = X + (size_t)TT * BATCH * NX;     // [T][BATCH]

    cudaFuncSetAttribute(inj_kernel,  cudaFuncAttributeMaxDynamicSharedMemorySize, INJ_SMEM);
    cudaFuncSetAttribute(scan_kernel, cudaFuncAttributeMaxDynamicSharedMemorySize, SCAN_SMEM);

    prep_kernel<<<NX, 256>>>(Aw, As);
    inj_kernel<<<dim3(8, (TT * BATCH) / 64), 256, INJ_SMEM>>>(U, D, Bw, Ew, X);
    scan_kernel<<<NCTA, 256, SCAN_SMEM>>>(x0, X, Y);
}